// round 1
// baseline (speedup 1.0000x reference)
#include <cuda_runtime.h>
#include <math.h>

#define NHEADS 12
#define HD 64
#define DMODEL 768
#define BATCH 4
#define SEQ 2048
#define MTOT (BATCH * SEQ)

// Scratch (allocation-free rule: __device__ globals)
__device__ float g_q[(size_t)BATCH * NHEADS * SEQ * HD];
__device__ float g_k[(size_t)BATCH * NHEADS * SEQ * HD];
__device__ float g_v[(size_t)BATCH * NHEADS * SEQ * HD];
__device__ float g_ctx[(size_t)MTOT * DMODEL];

// ---------------------------------------------------------------------------
// QKV projection: X[8192,768] @ W[768,768] -> head-split layout [b,h,n,d]
// 128x128x8 SGEMM, 256 threads, 8x8 per thread, float4 loads.
// blockIdx.z selects Wq/Wk/Wv.
// ---------------------------------------------------------------------------
__global__ __launch_bounds__(256) void qkv_gemm_kernel(
    const float* __restrict__ X,
    const float* __restrict__ Wq,
    const float* __restrict__ Wk,
    const float* __restrict__ Wv)
{
    const int K = DMODEL, NC = DMODEL;
    const float* W = (blockIdx.z == 0) ? Wq : (blockIdx.z == 1) ? Wk : Wv;
    float* Out = (blockIdx.z == 0) ? g_q : (blockIdx.z == 1) ? g_k : g_v;

    __shared__ float As[8][128];
    __shared__ float Bs[8][128];

    const int tid = threadIdx.x;
    const int row0 = blockIdx.y * 128;
    const int col0 = blockIdx.x * 128;
    const int a_row = tid >> 1;
    const int a_col = (tid & 1) << 2;
    const int b_row = tid >> 5;
    const int b_col = (tid & 31) << 2;
    const int ty = tid >> 4;
    const int tx = tid & 15;

    const float* Ap = X + (size_t)row0 * K;
    const float* Bp = W + col0;

    float acc[8][8];
#pragma unroll
    for (int i = 0; i < 8; i++)
#pragma unroll
        for (int j = 0; j < 8; j++) acc[i][j] = 0.f;

    for (int k0 = 0; k0 < K; k0 += 8) {
        float4 av = *(const float4*)(Ap + (size_t)a_row * K + k0 + a_col);
        As[a_col + 0][a_row] = av.x;
        As[a_col + 1][a_row] = av.y;
        As[a_col + 2][a_row] = av.z;
        As[a_col + 3][a_row] = av.w;
        float4 bv = *(const float4*)(Bp + (size_t)(k0 + b_row) * NC + b_col);
        *(float4*)&Bs[b_row][b_col] = bv;
        __syncthreads();
#pragma unroll
        for (int kk = 0; kk < 8; kk++) {
            float ar[8], br[8];
            *(float4*)&ar[0] = *(const float4*)&As[kk][ty * 8];
            *(float4*)&ar[4] = *(const float4*)&As[kk][ty * 8 + 4];
            *(float4*)&br[0] = *(const float4*)&Bs[kk][tx * 8];
            *(float4*)&br[4] = *(const float4*)&Bs[kk][tx * 8 + 4];
#pragma unroll
            for (int i = 0; i < 8; i++)
#pragma unroll
                for (int j = 0; j < 8; j++)
                    acc[i][j] = fmaf(ar[i], br[j], acc[i][j]);
        }
        __syncthreads();
    }

#pragma unroll
    for (int i = 0; i < 8; i++) {
        const int r = row0 + ty * 8 + i;
        const int b = r >> 11;       // / SEQ
        const int n = r & (SEQ - 1);
#pragma unroll
        for (int j = 0; j < 8; j++) {
            const int c = col0 + tx * 8 + j;
            const int h = c >> 6;    // / HD
            const int d = c & 63;
            Out[((size_t)(b * NHEADS + h) * SEQ + n) * HD + d] = acc[i][j];
        }
    }
}

// ---------------------------------------------------------------------------
// Output projection: g_ctx[8192,768] @ Wo[768,768] + bo -> d_out
// ---------------------------------------------------------------------------
__global__ __launch_bounds__(256) void out_gemm_kernel(
    const float* __restrict__ Wo, const float* __restrict__ bo,
    float* __restrict__ Out)
{
    const int K = DMODEL, NC = DMODEL;
    __shared__ float As[8][128];
    __shared__ float Bs[8][128];

    const int tid = threadIdx.x;
    const int row0 = blockIdx.y * 128;
    const int col0 = blockIdx.x * 128;
    const int a_row = tid >> 1;
    const int a_col = (tid & 1) << 2;
    const int b_row = tid >> 5;
    const int b_col = (tid & 31) << 2;
    const int ty = tid >> 4;
    const int tx = tid & 15;

    const float* Ap = g_ctx + (size_t)row0 * K;
    const float* Bp = Wo + col0;

    float acc[8][8];
#pragma unroll
    for (int i = 0; i < 8; i++)
#pragma unroll
        for (int j = 0; j < 8; j++) acc[i][j] = 0.f;

    for (int k0 = 0; k0 < K; k0 += 8) {
        float4 av = *(const float4*)(Ap + (size_t)a_row * K + k0 + a_col);
        As[a_col + 0][a_row] = av.x;
        As[a_col + 1][a_row] = av.y;
        As[a_col + 2][a_row] = av.z;
        As[a_col + 3][a_row] = av.w;
        float4 bv = *(const float4*)(Bp + (size_t)(k0 + b_row) * NC + b_col);
        *(float4*)&Bs[b_row][b_col] = bv;
        __syncthreads();
#pragma unroll
        for (int kk = 0; kk < 8; kk++) {
            float ar[8], br[8];
            *(float4*)&ar[0] = *(const float4*)&As[kk][ty * 8];
            *(float4*)&ar[4] = *(const float4*)&As[kk][ty * 8 + 4];
            *(float4*)&br[0] = *(const float4*)&Bs[kk][tx * 8];
            *(float4*)&br[4] = *(const float4*)&Bs[kk][tx * 8 + 4];
#pragma unroll
            for (int i = 0; i < 8; i++)
#pragma unroll
                for (int j = 0; j < 8; j++)
                    acc[i][j] = fmaf(ar[i], br[j], acc[i][j]);
        }
        __syncthreads();
    }

#pragma unroll
    for (int i = 0; i < 8; i++) {
        const int r = row0 + ty * 8 + i;
#pragma unroll
        for (int j = 0; j < 8; j++) {
            const int c = col0 + tx * 8 + j;
            Out[(size_t)r * NC + c] = acc[i][j] + bo[c];
        }
    }
}

// ---------------------------------------------------------------------------
// Flash attention (fp32, causal). One block = 64 q-rows of one (b,h).
// 256 threads as 16x16, 4x4 S / 4x4 O per thread. Online softmax.
// Smem: Qt (transposed, pre-scaled), Kt/P shared buffer, V, reduce scratch.
// ---------------------------------------------------------------------------
#define PADW 68
#define ATTN_SMEM ((3 * 64 * PADW + 64 * 17 + 2 * 64) * 4)

__global__ __launch_bounds__(256) void attn_kernel()
{
    extern __shared__ float sm[];
    float* Qt   = sm;                    // [64][PADW] Qt[d][row], pre-scaled
    float* KP   = Qt + 64 * PADW;        // Kt[d][col] then reused as P[row][k]
    float* Vs   = KP + 64 * PADW;        // [k][d]
    float* red  = Vs + 64 * PADW;        // [64][17]
    float* m_sh = red + 64 * 17;         // [64]
    float* l_sh = m_sh + 64;             // [64]

    const int qt = (int)gridDim.x - 1 - (int)blockIdx.x;  // heavy blocks first
    const int bh = blockIdx.y;
    const float* qb = g_q + (size_t)bh * SEQ * HD;
    const float* kb = g_k + (size_t)bh * SEQ * HD;
    const float* vb = g_v + (size_t)bh * SEQ * HD;

    const int tid = threadIdx.x;
    const int ty = tid >> 4, tx = tid & 15;
    const int lr = tid >> 2;            // 0..63 (row loaded by this thread)
    const int lc = (tid & 3) << 4;      // 0,16,32,48
    const int q0 = qt * 64;

    // Load Q tile transposed + pre-scaled by 1/sqrt(64)
#pragma unroll
    for (int j = 0; j < 16; j += 4) {
        float4 v = *(const float4*)(qb + (size_t)(q0 + lr) * HD + lc + j);
        Qt[(lc + j + 0) * PADW + lr] = v.x * 0.125f;
        Qt[(lc + j + 1) * PADW + lr] = v.y * 0.125f;
        Qt[(lc + j + 2) * PADW + lr] = v.z * 0.125f;
        Qt[(lc + j + 3) * PADW + lr] = v.w * 0.125f;
    }
    if (tid < 64) { m_sh[tid] = -INFINITY; l_sh[tid] = 0.f; }

    float o[4][4];
#pragma unroll
    for (int i = 0; i < 4; i++)
#pragma unroll
        for (int j = 0; j < 4; j++) o[i][j] = 0.f;

    __syncthreads();

    for (int kt = 0; kt <= qt; kt++) {
        const int k0 = kt * 64;
        // Load K transposed, V row-major
#pragma unroll
        for (int j = 0; j < 16; j += 4) {
            float4 kv = *(const float4*)(kb + (size_t)(k0 + lr) * HD + lc + j);
            KP[(lc + j + 0) * PADW + lr] = kv.x;
            KP[(lc + j + 1) * PADW + lr] = kv.y;
            KP[(lc + j + 2) * PADW + lr] = kv.z;
            KP[(lc + j + 3) * PADW + lr] = kv.w;
            float4 vv = *(const float4*)(vb + (size_t)(k0 + lr) * HD + lc + j);
            *(float4*)&Vs[lr * PADW + lc + j] = vv;
        }
        __syncthreads();

        // S = Q K^T (pre-scaled)
        float s[4][4];
#pragma unroll
        for (int i = 0; i < 4; i++)
#pragma unroll
            for (int j = 0; j < 4; j++) s[i][j] = 0.f;

#pragma unroll 4
        for (int d = 0; d < 64; d++) {
            float4 qv = *(const float4*)&Qt[d * PADW + ty * 4];
            float4 kv = *(const float4*)&KP[d * PADW + tx * 4];
            float qa[4] = {qv.x, qv.y, qv.z, qv.w};
            float ka[4] = {kv.x, kv.y, kv.z, kv.w};
#pragma unroll
            for (int i = 0; i < 4; i++)
#pragma unroll
                for (int j = 0; j < 4; j++)
                    s[i][j] = fmaf(qa[i], ka[j], s[i][j]);
        }

        if (kt == qt) {  // causal mask on the diagonal tile
#pragma unroll
            for (int i = 0; i < 4; i++)
#pragma unroll
                for (int j = 0; j < 4; j++)
                    if (k0 + tx * 4 + j > q0 + ty * 4 + i) s[i][j] = -INFINITY;
        }

        // Partial row max -> red
#pragma unroll
        for (int i = 0; i < 4; i++) {
            float pm = fmaxf(fmaxf(s[i][0], s[i][1]), fmaxf(s[i][2], s[i][3]));
            red[(ty * 4 + i) * 17 + tx] = pm;
        }
        __syncthreads();

        float alpha[4], mnew[4], psum[4];
#pragma unroll
        for (int i = 0; i < 4; i++) {
            const int r = ty * 4 + i;
            float mt = red[r * 17];
#pragma unroll
            for (int jj = 1; jj < 16; jj++) mt = fmaxf(mt, red[r * 17 + jj]);
            const float mold = m_sh[r];
            mnew[i] = fmaxf(mold, mt);
            alpha[i] = __expf(mold - mnew[i]);
            float rs = 0.f;
#pragma unroll
            for (int j = 0; j < 4; j++) {
                s[i][j] = __expf(s[i][j] - mnew[i]);
                rs += s[i][j];
                KP[r * PADW + tx * 4 + j] = s[i][j];  // Kt reads done; reuse as P
            }
            psum[i] = rs;
#pragma unroll
            for (int j = 0; j < 4; j++) o[i][j] *= alpha[i];
        }
        __syncthreads();  // red-max & m_sh reads complete

#pragma unroll
        for (int i = 0; i < 4; i++) red[(ty * 4 + i) * 17 + tx] = psum[i];
        if (tx == 0) {
#pragma unroll
            for (int i = 0; i < 4; i++) m_sh[ty * 4 + i] = mnew[i];
        }
        __syncthreads();

        if (tx == 0) {
#pragma unroll
            for (int i = 0; i < 4; i++) {
                const int r = ty * 4 + i;
                float rsum = 0.f;
#pragma unroll
                for (int jj = 0; jj < 16; jj++) rsum += red[r * 17 + jj];
                l_sh[r] = l_sh[r] * alpha[i] + rsum;
            }
        }

        // O += P @ V
#pragma unroll 4
        for (int k = 0; k < 64; k++) {
            float4 vv = *(const float4*)&Vs[k * PADW + tx * 4];
            float va[4] = {vv.x, vv.y, vv.z, vv.w};
            float p[4];
#pragma unroll
            for (int i = 0; i < 4; i++) p[i] = KP[(ty * 4 + i) * PADW + k];
#pragma unroll
            for (int i = 0; i < 4; i++)
#pragma unroll
                for (int j = 0; j < 4; j++)
                    o[i][j] = fmaf(p[i], va[j], o[i][j]);
        }
        __syncthreads();  // protect KP/Vs/red for next tile; orders l_sh
    }

    // Epilogue: normalize, write ctx in [b,n,768] layout
    const int bb = bh / NHEADS;
    const int h = bh % NHEADS;
#pragma unroll
    for (int i = 0; i < 4; i++) {
        const int r = q0 + ty * 4 + i;
        const float linv = 1.f / l_sh[ty * 4 + i];
#pragma unroll
        for (int j = 0; j < 4; j++) {
            g_ctx[((size_t)(bb * SEQ + r)) * DMODEL + h * HD + tx * 4 + j] =
                o[i][j] * linv;
        }
    }
}

// ---------------------------------------------------------------------------
extern "C" void kernel_launch(void* const* d_in, const int* in_sizes, int n_in,
                              void* d_out, int out_size)
{
    const float* X  = (const float*)d_in[0];
    const float* Wq = (const float*)d_in[1];
    const float* Wk = (const float*)d_in[2];
    const float* Wv = (const float*)d_in[3];
    const float* Wo = (const float*)d_in[4];
    const float* bo = (const float*)d_in[5];
    float* Out = (float*)d_out;

    dim3 g1(DMODEL / 128, MTOT / 128, 3);
    qkv_gemm_kernel<<<g1, 256>>>(X, Wq, Wk, Wv);

    cudaFuncSetAttribute(attn_kernel,
                         cudaFuncAttributeMaxDynamicSharedMemorySize, ATTN_SMEM);
    dim3 g2(SEQ / 64, BATCH * NHEADS);
    attn_kernel<<<g2, 256, ATTN_SMEM>>>();

    dim3 g3(DMODEL / 128, MTOT / 128);
    out_gemm_kernel<<<g3, 256>>>(Wo, bo, Out);
}

// round 3
// speedup vs baseline: 1.4425x; 1.4425x over previous
#include <cuda_runtime.h>
#include <cuda_bf16.h>
#include <math.h>
#include <stdint.h>

#define NHEADS 12
#define HD 64
#define DMODEL 768
#define BATCH 4
#define SEQ 2048
#define MTOT (BATCH * SEQ)
#define KSPLIT (3 * DMODEL)   // 2304 : A=[hi|lo|hi]  B=[hi|hi|lo]

// ---------------- device scratch (allocation-free rule) ----------------
__device__ float g_q[(size_t)BATCH * NHEADS * SEQ * HD];
__device__ float g_k[(size_t)BATCH * NHEADS * SEQ * HD];
__device__ float g_v[(size_t)BATCH * NHEADS * SEQ * HD];
__device__ __nv_bfloat16 g_xc[(size_t)MTOT * KSPLIT];      // split X
__device__ __nv_bfloat16 g_cc[(size_t)MTOT * KSPLIT];      // split ctx
__device__ __nv_bfloat16 g_wqkv[(size_t)KSPLIT * KSPLIT];  // [N=2304][K=2304]
__device__ __nv_bfloat16 g_wo[(size_t)DMODEL * KSPLIT];    // [768][2304]

// ---------------- PTX helpers (sm_103 baseline: cp.async + ldmatrix + mma) --
__device__ __forceinline__ uint32_t smem_u32(const void* p) {
    uint32_t a;
    asm("{ .reg .u64 t; cvta.to.shared.u64 t, %1; cvt.u32.u64 %0, t; }"
        : "=r"(a) : "l"(p));
    return a;
}
#define CPA16(dst, src) \
    asm volatile("cp.async.cg.shared.global [%0], [%1], 16;" :: "r"(dst), "l"(src))
#define CPA_COMMIT() asm volatile("cp.async.commit_group;" ::: "memory")

__device__ __forceinline__ void ldsm4(uint32_t* r, uint32_t addr) {
    asm volatile("ldmatrix.sync.aligned.m8n8.x4.shared.b16 {%0,%1,%2,%3}, [%4];"
                 : "=r"(r[0]), "=r"(r[1]), "=r"(r[2]), "=r"(r[3]) : "r"(addr));
}
__device__ __forceinline__ void mma_bf16(float* d, const uint32_t* a,
                                         const uint32_t* b) {
    asm volatile(
        "mma.sync.aligned.m16n8k16.row.col.f32.bf16.bf16.f32 "
        "{%0,%1,%2,%3}, {%4,%5,%6,%7}, {%8,%9}, {%0,%1,%2,%3};"
        : "+f"(d[0]), "+f"(d[1]), "+f"(d[2]), "+f"(d[3])
        : "r"(a[0]), "r"(a[1]), "r"(a[2]), "r"(a[3]), "r"(b[0]), "r"(b[1]));
}
__device__ __forceinline__ uint32_t sw128(uint32_t o) {
    return o ^ ((o >> 3) & 0x70);
}

// ---------------- split-precision conversion ----------------
__global__ __launch_bounds__(256) void conv_a_kernel(
    const float* __restrict__ src, __nv_bfloat16* __restrict__ dst)
{
    int idx = blockIdx.x * 256 + threadIdx.x;
    if (idx >= MTOT * DMODEL) return;
    int m = idx / DMODEL, k = idx - m * DMODEL;
    float x = src[idx];
    __nv_bfloat16 hi = __float2bfloat16(x);
    __nv_bfloat16 lo = __float2bfloat16(x - __bfloat162float(hi));
    size_t base = (size_t)m * KSPLIT + k;
    dst[base] = hi;
    dst[base + DMODEL] = lo;
    dst[base + 2 * DMODEL] = hi;
}

// transpose W[k][n] -> Wc[n][seg*768+k]; segments [hi, hi, lo]
__global__ __launch_bounds__(256) void conv_w_kernel(
    const float* __restrict__ W, __nv_bfloat16* __restrict__ dst, int nofs)
{
    __shared__ float t[32][33];
    int tx = threadIdx.x & 31, ty = threadIdx.x >> 5;
    int k0 = blockIdx.y * 32, n0 = blockIdx.x * 32;
#pragma unroll
    for (int yy = ty; yy < 32; yy += 8)
        t[yy][tx] = W[(size_t)(k0 + yy) * DMODEL + n0 + tx];
    __syncthreads();
#pragma unroll
    for (int yy = ty; yy < 32; yy += 8) {
        int n = n0 + yy, k = k0 + tx;
        float x = t[tx][yy];
        __nv_bfloat16 hi = __float2bfloat16(x);
        __nv_bfloat16 lo = __float2bfloat16(x - __bfloat162float(hi));
        size_t base = (size_t)(nofs + n) * KSPLIT + k;
        dst[base] = hi;
        dst[base + DMODEL] = hi;
        dst[base + 2 * DMODEL] = lo;
    }
}

// ---------------- mma.sync GEMM ----------------
// C[128x128] tile = A[row0:+128, :2304] x B[col0:+128, :2304]^T
// 8 warps (4 along M x 2 along N), warp tile 32x64, K-chunk 64, double buffer.
// mode 0: scatter into g_q/g_k/g_v ([b,h,n,d]); mode 1: Out = C + bias
#define NK_CHUNKS (KSPLIT / 64)     // 36
#define GEMM_SMEM (2 * 32768)

__global__ __launch_bounds__(256) void mma_gemm_kernel(
    const __nv_bfloat16* __restrict__ A,
    const __nv_bfloat16* __restrict__ B,
    const float* __restrict__ bias,
    float* __restrict__ OutF, int mode)
{
    extern __shared__ char smem[];
    const uint32_t sb = smem_u32(smem);
    const int tid = threadIdx.x, wid = tid >> 5, lid = tid & 31;
    const int row0 = blockIdx.y * 128, col0 = blockIdx.x * 128;
    const int m0 = (wid & 3) * 32, n0 = (wid >> 2) * 64;

    const int seg = tid & 7;          // 16B column segment (k)
    const int rowq = tid >> 3;        // 0..31
    const __nv_bfloat16* Abase = A + (size_t)row0 * KSPLIT;
    const __nv_bfloat16* Bbase = B + (size_t)col0 * KSPLIT;

    float acc[2][8][4];
#pragma unroll
    for (int mf = 0; mf < 2; mf++)
#pragma unroll
        for (int nf = 0; nf < 8; nf++)
#pragma unroll
            for (int e = 0; e < 4; e++) acc[mf][nf][e] = 0.f;

    auto load_chunk = [&](int i, int bf) {
        const uint32_t bA = sb + bf * 32768;
        const uint32_t bB = bA + 16384;
        const size_t kofs = (size_t)i * 64 + seg * 8;
#pragma unroll
        for (int gg = 0; gg < 4; gg++) {
            const int r = rowq + gg * 32;
            const uint32_t sw = sw128((uint32_t)(r * 128 + seg * 16));
            CPA16(bA + sw, Abase + (size_t)r * KSPLIT + kofs);
            CPA16(bB + sw, Bbase + (size_t)r * KSPLIT + kofs);
        }
        CPA_COMMIT();
    };

    // lane-dependent ldmatrix addressing
    const int rowA = lid & 15;
    const int aoff = (lid >> 4) * 16;             // byte col offset
    const int rowB = ((lid >> 4) << 3) + (lid & 7);
    const int boff = ((lid >> 3) & 1) * 16;

    load_chunk(0, 0);
    for (int i = 0; i < NK_CHUNKS; i++) {
        if (i + 1 < NK_CHUNKS) {
            load_chunk(i + 1, (i + 1) & 1);
            asm volatile("cp.async.wait_group 1;" ::: "memory");
        } else {
            asm volatile("cp.async.wait_group 0;" ::: "memory");
        }
        __syncthreads();

        const uint32_t bufA = sb + (i & 1) * 32768;
        const uint32_t bufB = bufA + 16384;
#pragma unroll
        for (int ks = 0; ks < 4; ks++) {
            uint32_t a[2][4], b[4][4];
#pragma unroll
            for (int mf = 0; mf < 2; mf++)
                ldsm4(a[mf], bufA + sw128((uint32_t)((m0 + mf * 16 + rowA) * 128
                                                     + ks * 32 + aoff)));
#pragma unroll
            for (int bj = 0; bj < 4; bj++)
                ldsm4(b[bj], bufB + sw128((uint32_t)((n0 + bj * 16 + rowB) * 128
                                                     + ks * 32 + boff)));
#pragma unroll
            for (int mf = 0; mf < 2; mf++)
#pragma unroll
                for (int nf = 0; nf < 8; nf++)
                    mma_bf16(acc[mf][nf], a[mf], &b[nf >> 1][(nf & 1) * 2]);
        }
        __syncthreads();
    }

    // epilogue: fragment (g = lid>>2, tig = lid&3)
    const int g = lid >> 2, tig = lid & 3;
#pragma unroll
    for (int mf = 0; mf < 2; mf++) {
#pragma unroll
        for (int nf = 0; nf < 8; nf++) {
            const int c = col0 + n0 + nf * 8 + tig * 2;
#pragma unroll
            for (int rr = 0; rr < 2; rr++) {
                const int r = row0 + m0 + mf * 16 + g + rr * 8;
                const float v0 = acc[mf][nf][rr * 2 + 0];
                const float v1 = acc[mf][nf][rr * 2 + 1];
                if (mode == 0) {
                    const int w = c / DMODEL;
                    const int rem = c - w * DMODEL;
                    const int h = rem >> 6, d = rem & 63;
                    float* dst = (w == 0) ? g_q : (w == 1) ? g_k : g_v;
                    const int bb = r >> 11, n = r & (SEQ - 1);
                    float2* p = (float2*)(dst +
                        ((size_t)(bb * NHEADS + h) * SEQ + n) * HD + d);
                    *p = make_float2(v0, v1);
                } else {
                    float2* p = (float2*)(OutF + (size_t)r * DMODEL + c);
                    *p = make_float2(v0 + bias[c], v1 + bias[c + 1]);
                }
            }
        }
    }
}

// ---------------------------------------------------------------------------
// Flash attention (fp32, causal) — epilogue writes split bf16 ctx
// ---------------------------------------------------------------------------
#define PADW 68
#define ATTN_SMEM ((3 * 64 * PADW + 64 * 17 + 2 * 64) * 4)

__global__ __launch_bounds__(256) void attn_kernel()
{
    extern __shared__ float sm[];
    float* Qt   = sm;
    float* KP   = Qt + 64 * PADW;
    float* Vs   = KP + 64 * PADW;
    float* red  = Vs + 64 * PADW;
    float* m_sh = red + 64 * 17;
    float* l_sh = m_sh + 64;

    const int qt = (int)gridDim.x - 1 - (int)blockIdx.x;
    const int bh = blockIdx.y;
    const float* qb = g_q + (size_t)bh * SEQ * HD;
    const float* kb = g_k + (size_t)bh * SEQ * HD;
    const float* vb = g_v + (size_t)bh * SEQ * HD;

    const int tid = threadIdx.x;
    const int ty = tid >> 4, tx = tid & 15;
    const int lr = tid >> 2;
    const int lc = (tid & 3) << 4;
    const int q0 = qt * 64;

#pragma unroll
    for (int j = 0; j < 16; j += 4) {
        float4 v = *(const float4*)(qb + (size_t)(q0 + lr) * HD + lc + j);
        Qt[(lc + j + 0) * PADW + lr] = v.x * 0.125f;
        Qt[(lc + j + 1) * PADW + lr] = v.y * 0.125f;
        Qt[(lc + j + 2) * PADW + lr] = v.z * 0.125f;
        Qt[(lc + j + 3) * PADW + lr] = v.w * 0.125f;
    }
    if (tid < 64) { m_sh[tid] = -INFINITY; l_sh[tid] = 0.f; }

    float o[4][4];
#pragma unroll
    for (int i = 0; i < 4; i++)
#pragma unroll
        for (int j = 0; j < 4; j++) o[i][j] = 0.f;

    __syncthreads();

    for (int kt = 0; kt <= qt; kt++) {
        const int k0 = kt * 64;
#pragma unroll
        for (int j = 0; j < 16; j += 4) {
            float4 kv = *(const float4*)(kb + (size_t)(k0 + lr) * HD + lc + j);
            KP[(lc + j + 0) * PADW + lr] = kv.x;
            KP[(lc + j + 1) * PADW + lr] = kv.y;
            KP[(lc + j + 2) * PADW + lr] = kv.z;
            KP[(lc + j + 3) * PADW + lr] = kv.w;
            float4 vv = *(const float4*)(vb + (size_t)(k0 + lr) * HD + lc + j);
            *(float4*)&Vs[lr * PADW + lc + j] = vv;
        }
        __syncthreads();

        float s[4][4];
#pragma unroll
        for (int i = 0; i < 4; i++)
#pragma unroll
            for (int j = 0; j < 4; j++) s[i][j] = 0.f;

#pragma unroll 4
        for (int d = 0; d < 64; d++) {
            float4 qv = *(const float4*)&Qt[d * PADW + ty * 4];
            float4 kv = *(const float4*)&KP[d * PADW + tx * 4];
            float qa[4] = {qv.x, qv.y, qv.z, qv.w};
            float ka[4] = {kv.x, kv.y, kv.z, kv.w};
#pragma unroll
            for (int i = 0; i < 4; i++)
#pragma unroll
                for (int j = 0; j < 4; j++)
                    s[i][j] = fmaf(qa[i], ka[j], s[i][j]);
        }

        if (kt == qt) {
#pragma unroll
            for (int i = 0; i < 4; i++)
#pragma unroll
                for (int j = 0; j < 4; j++)
                    if (k0 + tx * 4 + j > q0 + ty * 4 + i) s[i][j] = -INFINITY;
        }

#pragma unroll
        for (int i = 0; i < 4; i++) {
            float pm = fmaxf(fmaxf(s[i][0], s[i][1]), fmaxf(s[i][2], s[i][3]));
            red[(ty * 4 + i) * 17 + tx] = pm;
        }
        __syncthreads();

        float alpha[4], mnew[4], psum[4];
#pragma unroll
        for (int i = 0; i < 4; i++) {
            const int r = ty * 4 + i;
            float mt = red[r * 17];
#pragma unroll
            for (int jj = 1; jj < 16; jj++) mt = fmaxf(mt, red[r * 17 + jj]);
            const float mold = m_sh[r];
            mnew[i] = fmaxf(mold, mt);
            alpha[i] = __expf(mold - mnew[i]);
            float rs = 0.f;
#pragma unroll
            for (int j = 0; j < 4; j++) {
                s[i][j] = __expf(s[i][j] - mnew[i]);
                rs += s[i][j];
                KP[r * PADW + tx * 4 + j] = s[i][j];
            }
            psum[i] = rs;
#pragma unroll
            for (int j = 0; j < 4; j++) o[i][j] *= alpha[i];
        }
        __syncthreads();

#pragma unroll
        for (int i = 0; i < 4; i++) red[(ty * 4 + i) * 17 + tx] = psum[i];
        if (tx == 0) {
#pragma unroll
            for (int i = 0; i < 4; i++) m_sh[ty * 4 + i] = mnew[i];
        }
        __syncthreads();

        if (tx == 0) {
#pragma unroll
            for (int i = 0; i < 4; i++) {
                const int r = ty * 4 + i;
                float rsum = 0.f;
#pragma unroll
                for (int jj = 0; jj < 16; jj++) rsum += red[r * 17 + jj];
                l_sh[r] = l_sh[r] * alpha[i] + rsum;
            }
        }

#pragma unroll 4
        for (int k = 0; k < 64; k++) {
            float4 vv = *(const float4*)&Vs[k * PADW + tx * 4];
            float va[4] = {vv.x, vv.y, vv.z, vv.w};
            float p[4];
#pragma unroll
            for (int i = 0; i < 4; i++) p[i] = KP[(ty * 4 + i) * PADW + k];
#pragma unroll
            for (int i = 0; i < 4; i++)
#pragma unroll
                for (int j = 0; j < 4; j++)
                    o[i][j] = fmaf(p[i], va[j], o[i][j]);
        }
        __syncthreads();
    }

    // Epilogue: normalize, write SPLIT bf16 ctx [b,n, seg*768 + h*64+d]
    const int bb = bh / NHEADS;
    const int h = bh % NHEADS;
#pragma unroll
    for (int i = 0; i < 4; i++) {
        const int r = q0 + ty * 4 + i;
        const float linv = 1.f / l_sh[ty * 4 + i];
        __nv_bfloat16* base =
            g_cc + (size_t)(bb * SEQ + r) * KSPLIT + h * HD + tx * 4;
#pragma unroll
        for (int j = 0; j < 4; j++) {
            const float val = o[i][j] * linv;
            __nv_bfloat16 hi = __float2bfloat16(val);
            __nv_bfloat16 lo = __float2bfloat16(val - __bfloat162float(hi));
            base[j] = hi;
            base[DMODEL + j] = lo;
            base[2 * DMODEL + j] = hi;
        }
    }
}

// ---------------------------------------------------------------------------
extern "C" void kernel_launch(void* const* d_in, const int* in_sizes, int n_in,
                              void* d_out, int out_size)
{
    const float* X  = (const float*)d_in[0];
    const float* Wq = (const float*)d_in[1];
    const float* Wk = (const float*)d_in[2];
    const float* Wv = (const float*)d_in[3];
    const float* Wo = (const float*)d_in[4];
    const float* bo = (const float*)d_in[5];
    float* Out = (float*)d_out;

    cudaFuncSetAttribute(mma_gemm_kernel,
                         cudaFuncAttributeMaxDynamicSharedMemorySize, GEMM_SMEM);
    cudaFuncSetAttribute(attn_kernel,
                         cudaFuncAttributeMaxDynamicSharedMemorySize, ATTN_SMEM);

    __nv_bfloat16 *xc_p, *cc_p, *wqkv_p, *wo_p;
    cudaGetSymbolAddress((void**)&xc_p, g_xc);
    cudaGetSymbolAddress((void**)&cc_p, g_cc);
    cudaGetSymbolAddress((void**)&wqkv_p, g_wqkv);
    cudaGetSymbolAddress((void**)&wo_p, g_wo);

    // split-precision conversions
    conv_a_kernel<<<(MTOT * DMODEL + 255) / 256, 256>>>(X, xc_p);
    dim3 wgrid(DMODEL / 32, DMODEL / 32);
    conv_w_kernel<<<wgrid, 256>>>(Wq, wqkv_p, 0);
    conv_w_kernel<<<wgrid, 256>>>(Wk, wqkv_p, DMODEL);
    conv_w_kernel<<<wgrid, 256>>>(Wv, wqkv_p, 2 * DMODEL);
    conv_w_kernel<<<wgrid, 256>>>(Wo, wo_p, 0);

    // fused QKV projection: [8192 x 2304] = Xc @ Wqkv^T (mma.sync bf16x3)
    dim3 g1(KSPLIT / 128, MTOT / 128);
    mma_gemm_kernel<<<g1, 256, GEMM_SMEM>>>(xc_p, wqkv_p, nullptr, nullptr, 0);

    // attention (fp32)
    dim3 g2(SEQ / 64, BATCH * NHEADS);
    attn_kernel<<<g2, 256, ATTN_SMEM>>>();

    // output projection: [8192 x 768] = Ctxc @ Wo^T + bo (mma.sync bf16x3)
    dim3 g3(DMODEL / 128, MTOT / 128);
    mma_gemm_kernel<<<g3, 256, GEMM_SMEM>>>(cc_p, wo_p, bo, Out, 1);
}

// round 4
// speedup vs baseline: 3.6224x; 2.5112x over previous
#include <cuda_runtime.h>
#include <cuda_bf16.h>
#include <math.h>
#include <stdint.h>

#define NHEADS 12
#define HD 64
#define DMODEL 768
#define BATCH 4
#define SEQ 2048
#define MTOT (BATCH * SEQ)
#define KSPLIT (3 * DMODEL)   // 2304 : A=[hi|lo|hi]  B=[hi|hi|lo]

// ---------------- device scratch (allocation-free rule) ----------------
__device__ float g_q[(size_t)BATCH * NHEADS * SEQ * HD];   // [b,h,n,d] (pre-scaled)
__device__ float g_k[(size_t)BATCH * NHEADS * SEQ * HD];   // [b,h,n,d]
__device__ float g_v[(size_t)BATCH * NHEADS * SEQ * HD];   // [b,h,d,n] TRANSPOSED
__device__ __nv_bfloat16 g_xc[(size_t)MTOT * KSPLIT];
__device__ __nv_bfloat16 g_cc[(size_t)MTOT * KSPLIT];
__device__ __nv_bfloat16 g_wqkv[(size_t)KSPLIT * KSPLIT];
__device__ __nv_bfloat16 g_wo[(size_t)DMODEL * KSPLIT];

// ---------------- PTX helpers ----------------
__device__ __forceinline__ uint32_t smem_u32(const void* p) {
    uint32_t a;
    asm("{ .reg .u64 t; cvta.to.shared.u64 t, %1; cvt.u32.u64 %0, t; }"
        : "=r"(a) : "l"(p));
    return a;
}
#define CPA16(dst, src) \
    asm volatile("cp.async.cg.shared.global [%0], [%1], 16;" :: "r"(dst), "l"(src))
#define CPA_COMMIT() asm volatile("cp.async.commit_group;" ::: "memory")

__device__ __forceinline__ void ldsm4(uint32_t* r, uint32_t addr) {
    asm volatile("ldmatrix.sync.aligned.m8n8.x4.shared.b16 {%0,%1,%2,%3}, [%4];"
                 : "=r"(r[0]), "=r"(r[1]), "=r"(r[2]), "=r"(r[3]) : "r"(addr));
}
__device__ __forceinline__ void mma_bf16(float* d, const uint32_t* a,
                                         const uint32_t* b) {
    asm volatile(
        "mma.sync.aligned.m16n8k16.row.col.f32.bf16.bf16.f32 "
        "{%0,%1,%2,%3}, {%4,%5,%6,%7}, {%8,%9}, {%0,%1,%2,%3};"
        : "+f"(d[0]), "+f"(d[1]), "+f"(d[2]), "+f"(d[3])
        : "r"(a[0]), "r"(a[1]), "r"(a[2]), "r"(a[3]), "r"(b[0]), "r"(b[1]));
}
__device__ __forceinline__ void mma_tf32(float* d, const uint32_t* a,
                                         const uint32_t* b) {
    asm volatile(
        "mma.sync.aligned.m16n8k8.row.col.f32.tf32.tf32.f32 "
        "{%0,%1,%2,%3}, {%4,%5,%6,%7}, {%8,%9}, {%0,%1,%2,%3};"
        : "+f"(d[0]), "+f"(d[1]), "+f"(d[2]), "+f"(d[3])
        : "r"(a[0]), "r"(a[1]), "r"(a[2]), "r"(a[3]), "r"(b[0]), "r"(b[1]));
}
__device__ __forceinline__ uint32_t sw128(uint32_t o) {
    return o ^ ((o >> 3) & 0x70);
}
// 256B-row swizzle: 16B segment XOR low 3 row bits
__device__ __forceinline__ uint32_t swz256(int row, int seg) {
    return (uint32_t)(row * 256 + (((seg ^ row) & 15) << 4) + ((seg & ~15) << 4));
}

// ---------------- split-precision conversion ----------------
__global__ __launch_bounds__(256) void conv_a_kernel(
    const float* __restrict__ src, __nv_bfloat16* __restrict__ dst)
{
    int idx = blockIdx.x * 256 + threadIdx.x;
    if (idx >= MTOT * DMODEL) return;
    int m = idx / DMODEL, k = idx - m * DMODEL;
    float x = src[idx];
    __nv_bfloat16 hi = __float2bfloat16(x);
    __nv_bfloat16 lo = __float2bfloat16(x - __bfloat162float(hi));
    size_t base = (size_t)m * KSPLIT + k;
    dst[base] = hi;
    dst[base + DMODEL] = lo;
    dst[base + 2 * DMODEL] = hi;
}

__global__ __launch_bounds__(256) void conv_w_kernel(
    const float* __restrict__ W, __nv_bfloat16* __restrict__ dst, int nofs)
{
    __shared__ float t[32][33];
    int tx = threadIdx.x & 31, ty = threadIdx.x >> 5;
    int k0 = blockIdx.y * 32, n0 = blockIdx.x * 32;
#pragma unroll
    for (int yy = ty; yy < 32; yy += 8)
        t[yy][tx] = W[(size_t)(k0 + yy) * DMODEL + n0 + tx];
    __syncthreads();
#pragma unroll
    for (int yy = ty; yy < 32; yy += 8) {
        int n = n0 + yy, k = k0 + tx;
        float x = t[tx][yy];
        __nv_bfloat16 hi = __float2bfloat16(x);
        __nv_bfloat16 lo = __float2bfloat16(x - __bfloat162float(hi));
        size_t base = (size_t)(nofs + n) * KSPLIT + k;
        dst[base] = hi;
        dst[base + DMODEL] = hi;
        dst[base + 2 * DMODEL] = lo;
    }
}

// ---------------- mma.sync split-bf16 GEMM ----------------
#define NK_CHUNKS (KSPLIT / 64)
#define GEMM_SMEM (2 * 32768)

__global__ __launch_bounds__(256) void mma_gemm_kernel(
    const __nv_bfloat16* __restrict__ A,
    const __nv_bfloat16* __restrict__ B,
    const float* __restrict__ bias,
    float* __restrict__ OutF, int mode)
{
    extern __shared__ char smem[];
    const uint32_t sb = smem_u32(smem);
    const int tid = threadIdx.x, wid = tid >> 5, lid = tid & 31;
    const int row0 = blockIdx.y * 128, col0 = blockIdx.x * 128;
    const int m0 = (wid & 3) * 32, n0 = (wid >> 2) * 64;

    const int seg = tid & 7;
    const int rowq = tid >> 3;
    const __nv_bfloat16* Abase = A + (size_t)row0 * KSPLIT;
    const __nv_bfloat16* Bbase = B + (size_t)col0 * KSPLIT;

    float acc[2][8][4];
#pragma unroll
    for (int mf = 0; mf < 2; mf++)
#pragma unroll
        for (int nf = 0; nf < 8; nf++)
#pragma unroll
            for (int e = 0; e < 4; e++) acc[mf][nf][e] = 0.f;

    auto load_chunk = [&](int i, int bf) {
        const uint32_t bA = sb + bf * 32768;
        const uint32_t bB = bA + 16384;
        const size_t kofs = (size_t)i * 64 + seg * 8;
#pragma unroll
        for (int gg = 0; gg < 4; gg++) {
            const int r = rowq + gg * 32;
            const uint32_t sw = sw128((uint32_t)(r * 128 + seg * 16));
            CPA16(bA + sw, Abase + (size_t)r * KSPLIT + kofs);
            CPA16(bB + sw, Bbase + (size_t)r * KSPLIT + kofs);
        }
        CPA_COMMIT();
    };

    const int rowA = lid & 15;
    const int aoff = (lid >> 4) * 16;
    const int rowB = ((lid >> 4) << 3) + (lid & 7);
    const int boff = ((lid >> 3) & 1) * 16;

    load_chunk(0, 0);
    for (int i = 0; i < NK_CHUNKS; i++) {
        if (i + 1 < NK_CHUNKS) {
            load_chunk(i + 1, (i + 1) & 1);
            asm volatile("cp.async.wait_group 1;" ::: "memory");
        } else {
            asm volatile("cp.async.wait_group 0;" ::: "memory");
        }
        __syncthreads();

        const uint32_t bufA = sb + (i & 1) * 32768;
        const uint32_t bufB = bufA + 16384;
#pragma unroll
        for (int ks = 0; ks < 4; ks++) {
            uint32_t a[2][4], b[4][4];
#pragma unroll
            for (int mf = 0; mf < 2; mf++)
                ldsm4(a[mf], bufA + sw128((uint32_t)((m0 + mf * 16 + rowA) * 128
                                                     + ks * 32 + aoff)));
#pragma unroll
            for (int bj = 0; bj < 4; bj++)
                ldsm4(b[bj], bufB + sw128((uint32_t)((n0 + bj * 16 + rowB) * 128
                                                     + ks * 32 + boff)));
#pragma unroll
            for (int mf = 0; mf < 2; mf++)
#pragma unroll
                for (int nf = 0; nf < 8; nf++)
                    mma_bf16(acc[mf][nf], a[mf], &b[nf >> 1][(nf & 1) * 2]);
        }
        __syncthreads();
    }

    const int g = lid >> 2, tig = lid & 3;
#pragma unroll
    for (int mf = 0; mf < 2; mf++) {
#pragma unroll
        for (int nf = 0; nf < 8; nf++) {
            const int c = col0 + n0 + nf * 8 + tig * 2;
#pragma unroll
            for (int rr = 0; rr < 2; rr++) {
                const int r = row0 + m0 + mf * 16 + g + rr * 8;
                const float v0 = acc[mf][nf][rr * 2 + 0];
                const float v1 = acc[mf][nf][rr * 2 + 1];
                if (mode == 0) {
                    const int w = c / DMODEL;
                    const int rem = c - w * DMODEL;
                    const int h = rem >> 6, d = rem & 63;
                    const int bb = r >> 11, n = r & (SEQ - 1);
                    if (w == 0) {        // Q: pre-scale by 1/sqrt(64)
                        float2* p = (float2*)(g_q +
                            ((size_t)(bb * NHEADS + h) * SEQ + n) * HD + d);
                        *p = make_float2(v0 * 0.125f, v1 * 0.125f);
                    } else if (w == 1) { // K: [b,h,n,d]
                        float2* p = (float2*)(g_k +
                            ((size_t)(bb * NHEADS + h) * SEQ + n) * HD + d);
                        *p = make_float2(v0, v1);
                    } else {             // V: TRANSPOSED [b,h,d,n]
                        float* p = g_v +
                            ((size_t)(bb * NHEADS + h) * HD + d) * SEQ + n;
                        p[0] = v0;
                        p[SEQ] = v1;
                    }
                } else {
                    float2* p = (float2*)(OutF + (size_t)r * DMODEL + c);
                    *p = make_float2(v0 + bias[c], v1 + bias[c + 1]);
                }
            }
        }
    }
}

// ---------------------------------------------------------------------------
// Tensor-core flash attention (tf32 mma.sync, causal)
// 256 threads, warp w owns q-rows [w*16, w*16+16) of a 128-row q-tile.
// ---------------------------------------------------------------------------
#define ATT_SMEM 131072

__global__ __launch_bounds__(256, 1) void attn_mma_kernel()
{
    extern __shared__ char smc[];
    const uint32_t sb = smem_u32(smc);
    const uint32_t Qs = sb;              // [128][64] f32 swizzled  32KB
    const uint32_t Kb = sb + 32768;      // 2 x [64][64]            32KB
    const uint32_t Vb = sb + 65536;      // 2 x [64][64] (Vt)       32KB
    const uint32_t Pb = sb + 98304;      // [128][64]               32KB

    const int tid = threadIdx.x, w = tid >> 5, lid = tid & 31;
    const int g = lid >> 2, tig = lid & 3;
    const int qt = (int)gridDim.x - 1 - (int)blockIdx.x;   // heavy first
    const int bh = blockIdx.y;
    const int q0 = qt * 128;
    const int nk = 2 * qt + 2;

    const float* qb = g_q + (size_t)bh * SEQ * HD;
    const float* kb = g_k + (size_t)bh * SEQ * HD;
    const float* vtb = g_v + (size_t)bh * HD * SEQ;   // [d][n]

    // ---- Q tile (2048 16B chunks) ----
#pragma unroll
    for (int c = 0; c < 8; c++) {
        const int idx = tid + c * 256, row = idx >> 4, seg = idx & 15;
        CPA16(Qs + swz256(row, seg), qb + (size_t)(q0 + row) * HD + seg * 4);
    }
    auto load_kv = [&](int i, int bf) {
        const int k0 = i * 64;
        const uint32_t kd = Kb + bf * 16384, vd = Vb + bf * 16384;
#pragma unroll
        for (int c = 0; c < 4; c++) {
            const int idx = tid + c * 256, row = idx >> 4, seg = idx & 15;
            const uint32_t sw = swz256(row, seg);
            CPA16(kd + sw, kb + (size_t)(k0 + row) * HD + seg * 4);
            CPA16(vd + sw, vtb + (size_t)row * SEQ + k0 + seg * 4);
        }
        CPA_COMMIT();
    };
    load_kv(0, 0);                        // group: Q chunks + KV0
    if (nk > 1) load_kv(1, 1);
    if (nk > 1) asm volatile("cp.async.wait_group 1;" ::: "memory");
    else        asm volatile("cp.async.wait_group 0;" ::: "memory");
    __syncthreads();

    // ---- Q fragments (held in registers for whole block) ----
    const int arow = w * 16 + (lid & 15);
    const int asoff = lid >> 4;
    uint32_t qf[8][4];
#pragma unroll
    for (int kk = 0; kk < 8; kk++)
        ldsm4(qf[kk], Qs + swz256(arow, kk * 2 + asoff));

    const int brow = lid & 7, bsoff = lid >> 3;

    float oacc[8][4];
#pragma unroll
    for (int nf = 0; nf < 8; nf++)
#pragma unroll
        for (int e = 0; e < 4; e++) oacc[nf][e] = 0.f;
    float m0 = -INFINITY, m1 = -INFINITY, l0 = 0.f, l1 = 0.f;

    const int qr0 = q0 + w * 16 + g, qr1 = qr0 + 8;

    for (int i = 0; i < nk; i++) {
        const uint32_t Kc = Kb + (i & 1) * 16384;
        const uint32_t Vc = Vb + (i & 1) * 16384;

        // ---- S = Q K^T ----
        float sacc[8][4];
#pragma unroll
        for (int nf = 0; nf < 8; nf++)
#pragma unroll
            for (int e = 0; e < 4; e++) sacc[nf][e] = 0.f;
#pragma unroll
        for (int nf = 0; nf < 8; nf++) {
            const int krow = nf * 8 + brow;
#pragma unroll
            for (int k2 = 0; k2 < 4; k2++) {
                uint32_t b[4];
                ldsm4(b, Kc + swz256(krow, k2 * 4 + bsoff));
                mma_tf32(sacc[nf], qf[2 * k2], b);
                mma_tf32(sacc[nf], qf[2 * k2 + 1], b + 2);
            }
        }

        // ---- causal mask (only last two k-tiles) ----
        const int k0 = i * 64;
        if (i >= 2 * qt) {
#pragma unroll
            for (int nf = 0; nf < 8; nf++) {
                const int c0 = k0 + nf * 8 + 2 * tig;
                if (c0 > qr0) sacc[nf][0] = -INFINITY;
                if (c0 + 1 > qr0) sacc[nf][1] = -INFINITY;
                if (c0 > qr1) sacc[nf][2] = -INFINITY;
                if (c0 + 1 > qr1) sacc[nf][3] = -INFINITY;
            }
        }

        // ---- row max across thread-local + quad ----
        float mt0 = sacc[0][0], mt1 = sacc[0][2];
#pragma unroll
        for (int nf = 0; nf < 8; nf++) {
            mt0 = fmaxf(mt0, fmaxf(sacc[nf][0], sacc[nf][1]));
            mt1 = fmaxf(mt1, fmaxf(sacc[nf][2], sacc[nf][3]));
        }
        mt0 = fmaxf(mt0, __shfl_xor_sync(0xffffffff, mt0, 1));
        mt0 = fmaxf(mt0, __shfl_xor_sync(0xffffffff, mt0, 2));
        mt1 = fmaxf(mt1, __shfl_xor_sync(0xffffffff, mt1, 1));
        mt1 = fmaxf(mt1, __shfl_xor_sync(0xffffffff, mt1, 2));

        const float mn0 = fmaxf(m0, mt0), mn1 = fmaxf(m1, mt1);
        const float a0 = __expf(m0 - mn0), a1 = __expf(m1 - mn1);
        m0 = mn0; m1 = mn1;

        __syncwarp();   // previous ldsm reads of Pb complete
        float rs0 = 0.f, rs1 = 0.f;
        const int prow0 = w * 16 + g, prow1 = prow0 + 8;
#pragma unroll
        for (int nf = 0; nf < 8; nf++) {
            const float p0 = __expf(sacc[nf][0] - mn0);
            const float p1 = __expf(sacc[nf][1] - mn0);
            const float p2 = __expf(sacc[nf][2] - mn1);
            const float p3 = __expf(sacc[nf][3] - mn1);
            rs0 += p0 + p1; rs1 += p2 + p3;
            const int col = nf * 8 + 2 * tig;
            const int seg = col >> 2, off = (col & 3) * 4;
            asm volatile("st.shared.v2.f32 [%0], {%1,%2};"
                         :: "r"(Pb + swz256(prow0, seg) + off),
                            "f"(p0), "f"(p1) : "memory");
            asm volatile("st.shared.v2.f32 [%0], {%1,%2};"
                         :: "r"(Pb + swz256(prow1, seg) + off),
                            "f"(p2), "f"(p3) : "memory");
        }
        rs0 += __shfl_xor_sync(0xffffffff, rs0, 1);
        rs0 += __shfl_xor_sync(0xffffffff, rs0, 2);
        rs1 += __shfl_xor_sync(0xffffffff, rs1, 1);
        rs1 += __shfl_xor_sync(0xffffffff, rs1, 2);
        l0 = l0 * a0 + rs0;
        l1 = l1 * a1 + rs1;
#pragma unroll
        for (int nf = 0; nf < 8; nf++) {
            oacc[nf][0] *= a0; oacc[nf][1] *= a0;
            oacc[nf][2] *= a1; oacc[nf][3] *= a1;
        }
        __syncwarp();   // P stores visible to whole warp

        // ---- O += P V ----
#pragma unroll
        for (int k2 = 0; k2 < 4; k2++) {
            uint32_t pa[2][4];
            ldsm4(pa[0], Pb + swz256(arow, (2 * k2) * 2 + asoff));
            ldsm4(pa[1], Pb + swz256(arow, (2 * k2 + 1) * 2 + asoff));
#pragma unroll
            for (int nf = 0; nf < 8; nf++) {
                uint32_t vb4[4];
                ldsm4(vb4, Vc + swz256(nf * 8 + brow, k2 * 4 + bsoff));
                mma_tf32(oacc[nf], pa[0], vb4);
                mma_tf32(oacc[nf], pa[1], vb4 + 2);
            }
        }

        __syncthreads();                 // all warps done with K/V bufs
        if (i + 2 < nk) load_kv(i + 2, i & 1);
        if (i + 1 < nk) {
            if (i + 2 < nk)
                asm volatile("cp.async.wait_group 1;" ::: "memory");
            else
                asm volatile("cp.async.wait_group 0;" ::: "memory");
            __syncthreads();
        }
    }

    // ---- epilogue: normalize + write split bf16 ctx ----
    const int bb = bh / NHEADS, h = bh - bb * NHEADS;
    const float inv0 = 1.f / l0, inv1 = 1.f / l1;
#pragma unroll
    for (int nf = 0; nf < 8; nf++) {
        const int c = nf * 8 + 2 * tig;
#pragma unroll
        for (int rr = 0; rr < 2; rr++) {
            const int r = (rr == 0) ? qr0 : qr1;
            const float v0 = oacc[nf][rr * 2 + 0] * (rr == 0 ? inv0 : inv1);
            const float v1 = oacc[nf][rr * 2 + 1] * (rr == 0 ? inv0 : inv1);
            __nv_bfloat16 h0 = __float2bfloat16(v0);
            __nv_bfloat16 h1 = __float2bfloat16(v1);
            __nv_bfloat16 e0 = __float2bfloat16(v0 - __bfloat162float(h0));
            __nv_bfloat16 e1 = __float2bfloat16(v1 - __bfloat162float(h1));
            __nv_bfloat16* base =
                g_cc + (size_t)(bb * SEQ + r) * KSPLIT + h * HD + c;
            *(__nv_bfloat162*)base = __nv_bfloat162(h0, h1);
            *(__nv_bfloat162*)(base + DMODEL) = __nv_bfloat162(e0, e1);
            *(__nv_bfloat162*)(base + 2 * DMODEL) = __nv_bfloat162(h0, h1);
        }
    }
}

// ---------------------------------------------------------------------------
extern "C" void kernel_launch(void* const* d_in, const int* in_sizes, int n_in,
                              void* d_out, int out_size)
{
    const float* X  = (const float*)d_in[0];
    const float* Wq = (const float*)d_in[1];
    const float* Wk = (const float*)d_in[2];
    const float* Wv = (const float*)d_in[3];
    const float* Wo = (const float*)d_in[4];
    const float* bo = (const float*)d_in[5];
    float* Out = (float*)d_out;

    cudaFuncSetAttribute(mma_gemm_kernel,
                         cudaFuncAttributeMaxDynamicSharedMemorySize, GEMM_SMEM);
    cudaFuncSetAttribute(attn_mma_kernel,
                         cudaFuncAttributeMaxDynamicSharedMemorySize, ATT_SMEM);

    __nv_bfloat16 *xc_p, *cc_p, *wqkv_p, *wo_p;
    cudaGetSymbolAddress((void**)&xc_p, g_xc);
    cudaGetSymbolAddress((void**)&cc_p, g_cc);
    cudaGetSymbolAddress((void**)&wqkv_p, g_wqkv);
    cudaGetSymbolAddress((void**)&wo_p, g_wo);

    conv_a_kernel<<<(MTOT * DMODEL + 255) / 256, 256>>>(X, xc_p);
    dim3 wgrid(DMODEL / 32, DMODEL / 32);
    conv_w_kernel<<<wgrid, 256>>>(Wq, wqkv_p, 0);
    conv_w_kernel<<<wgrid, 256>>>(Wk, wqkv_p, DMODEL);
    conv_w_kernel<<<wgrid, 256>>>(Wv, wqkv_p, 2 * DMODEL);
    conv_w_kernel<<<wgrid, 256>>>(Wo, wo_p, 0);

    dim3 g1(KSPLIT / 128, MTOT / 128);
    mma_gemm_kernel<<<g1, 256, GEMM_SMEM>>>(xc_p, wqkv_p, nullptr, nullptr, 0);

    dim3 g2(SEQ / 128, BATCH * NHEADS);
    attn_mma_kernel<<<g2, 256, ATT_SMEM>>>();

    dim3 g3(DMODEL / 128, MTOT / 128);
    mma_gemm_kernel<<<g3, 256, GEMM_SMEM>>>(cc_p, wo_p, bo, Out, 1);
}